// round 12
// baseline (speedup 1.0000x reference)
#include <cuda_runtime.h>
#include <cuda_fp16.h>

#define BATCH 2
#define CCH   256
#define NHEAD 8
#define HDIM  32
#define NGRP  32
#define SEQ   4096

typedef __half h16;

// Scratch (allocation-free: __device__ globals)
__device__ float g_stats[BATCH * NGRP * 2];         // mean, rstd per (b,g)
__device__ h16   g_ht[BATCH * SEQ * CCH];           // h transposed [b][s][c]
__device__ h16   g_qkv[BATCH * 3 * CCH * SEQ];      // Q(pre-scaled),K,V [b][3C][s]
__device__ h16   g_aot[BATCH * SEQ * CCH];          // attn out [b][s][c]
__device__ h16   g_wq[3 * CCH * CCH];               // qkv_w fp16
__device__ h16   g_wp[CCH * CCH];                   // proj_w fp16

__device__ __forceinline__ void mmaf16(
    float& d0, float& d1, float& d2, float& d3,
    unsigned a0, unsigned a1, unsigned a2, unsigned a3,
    unsigned b0, unsigned b1)
{
    asm volatile(
        "mma.sync.aligned.m16n8k16.row.col.f32.f16.f16.f32 "
        "{%0,%1,%2,%3}, {%4,%5,%6,%7}, {%8,%9}, {%0,%1,%2,%3};"
        : "+f"(d0), "+f"(d1), "+f"(d2), "+f"(d3)
        : "r"(a0), "r"(a1), "r"(a2), "r"(a3), "r"(b0), "r"(b1));
}

__device__ __forceinline__ unsigned packh2(float lo, float hi) {
    __half2 p = __floats2half2_rn(lo, hi);
    return *reinterpret_cast<unsigned*>(&p);
}

// pack two f32 scores to f16x2, then 2^x on both halves with ONE MUFU op
__device__ __forceinline__ unsigned ex2pair(float lo, float hi) {
    unsigned c, y;
    asm("cvt.rn.f16x2.f32 %0, %1, %2;" : "=r"(c) : "f"(hi), "f"(lo));
    asm("ex2.approx.f16x2 %0, %1;" : "=r"(y) : "r"(c));
    return y;
}

__device__ __forceinline__ unsigned su32(const void* p) {
    return (unsigned)__cvta_generic_to_shared(p);
}
__device__ __forceinline__ void ldsm4(unsigned& r0, unsigned& r1, unsigned& r2,
                                      unsigned& r3, unsigned a) {
    asm volatile("ldmatrix.sync.aligned.m8n8.x4.shared.b16 {%0,%1,%2,%3},[%4];"
                 : "=r"(r0), "=r"(r1), "=r"(r2), "=r"(r3) : "r"(a));
}
__device__ __forceinline__ void ldsm4t(unsigned& r0, unsigned& r1, unsigned& r2,
                                       unsigned& r3, unsigned a) {
    asm volatile("ldmatrix.sync.aligned.m8n8.x4.trans.shared.b16 {%0,%1,%2,%3},[%4];"
                 : "=r"(r0), "=r"(r1), "=r"(r2), "=r"(r3) : "r"(a));
}
__device__ __forceinline__ void cpasync16(unsigned dst, const void* src) {
    asm volatile("cp.async.cg.shared.global [%0], [%1], 16;" :: "r"(dst), "l"(src));
}
#define CP_COMMIT() asm volatile("cp.async.commit_group;" ::: "memory")
#define CP_WAIT0()  asm volatile("cp.async.wait_group 0;" ::: "memory")

// ---------------------------------------------------------------------------
// Prep: blocks [0,64) -> GN stats; blocks [64,448) -> weights fp16
// ---------------------------------------------------------------------------
__global__ __launch_bounds__(512) void prep_kernel(
    const float* __restrict__ x, float* __restrict__ stats,
    const float* __restrict__ qw, const float* __restrict__ pw,
    h16* __restrict__ oq, h16* __restrict__ op)
{
    const int tid = threadIdx.x;
    if (blockIdx.x >= 64) {
        int i = (blockIdx.x - 64) * 512 + tid;
        oq[i] = __float2half(qw[i]);
        if (i < CCH * CCH) op[i] = __float2half(pw[i]);
        return;
    }
    const int g = blockIdx.x & 31, b = blockIdx.x >> 5;
    const float4* xp = reinterpret_cast<const float4*>(x + ((size_t)b * CCH + g * 8) * SEQ);

    float s = 0.f, s2 = 0.f;
    #pragma unroll 4
    for (int i = tid; i < 8192; i += 512) {
        float4 v = xp[i];
        s  += v.x + v.y + v.z + v.w;
        s2 += v.x * v.x + v.y * v.y + v.z * v.z + v.w * v.w;
    }
    #pragma unroll
    for (int o = 16; o; o >>= 1) {
        s  += __shfl_xor_sync(0xFFFFFFFFu, s, o);
        s2 += __shfl_xor_sync(0xFFFFFFFFu, s2, o);
    }
    __shared__ float ss[16], ss2[16];
    int w = tid >> 5;
    if ((tid & 31) == 0) { ss[w] = s; ss2[w] = s2; }
    __syncthreads();
    if (tid == 0) {
        float a = 0.f, a2 = 0.f;
        #pragma unroll
        for (int j = 0; j < 16; j++) { a += ss[j]; a2 += ss2[j]; }
        const float invN = 1.f / 32768.f;
        float mean = a * invN;
        float var  = a2 * invN - mean * mean;
        stats[(b * NGRP + g) * 2]     = mean;
        stats[(b * NGRP + g) * 2 + 1] = rsqrtf(var + 1e-6f);
    }
}

// ---------------------------------------------------------------------------
// Fused normalize + transpose: x fp32 [b][c][s] -> ht fp16 [b][s][c]
// ---------------------------------------------------------------------------
__global__ __launch_bounds__(256) void normt_kernel(
    const float* __restrict__ x, const float* __restrict__ gamma,
    const float* __restrict__ beta, const float* __restrict__ stats,
    h16* __restrict__ out)
{
    const int s0 = blockIdx.x * 32, c0 = blockIdx.y * 32, b = blockIdx.z;
    __shared__ float T[32][33];
    const int t = threadIdx.x;
    {
        int r = t >> 3, cc = (t & 7) * 4;
        int c = c0 + r;
        int grp = c >> 3;
        float mean = stats[(b * NGRP + grp) * 2];
        float rstd = stats[(b * NGRP + grp) * 2 + 1];
        float ga = gamma[c] * rstd;
        float be = beta[c] - mean * ga;
        float4 v = *reinterpret_cast<const float4*>(
            x + ((size_t)b * CCH + c) * SEQ + s0 + cc);
        T[r][cc]     = v.x * ga + be;
        T[r][cc + 1] = v.y * ga + be;
        T[r][cc + 2] = v.z * ga + be;
        T[r][cc + 3] = v.w * ga + be;
    }
    __syncthreads();
    {
        int sr = t >> 3, c4 = (t & 7) * 4;
        uint2 u;
        u.x = packh2(T[c4][sr], T[c4 + 1][sr]);
        u.y = packh2(T[c4 + 2][sr], T[c4 + 3][sr]);
        *reinterpret_cast<uint2*>(out + ((size_t)b * SEQ + s0 + sr) * CCH + c0 + c4) = u;
    }
}

// ---------------------------------------------------------------------------
// fp16 tensor-core GEMM, double-buffered. Block tile (MF*32) x 128, 8 warps.
// MODE 0 (MF=4): qkv -> fp16 [b][3C][s], Q rows pre-scaled by log2(e)/sqrt(d)
// MODE 1 (MF=2): proj -> fp32 out = acc + bias + residual
// ---------------------------------------------------------------------------
template<int MODE, int MF>
__global__ __launch_bounds__(256, 2) void gemm_mma(
    const h16* __restrict__ W, const h16* __restrict__ X,
    const float* __restrict__ bias, const float* __restrict__ resid,
    float* __restrict__ out_f, h16* __restrict__ out_h)
{
    const int BM = MF * 32;
    const int n0 = blockIdx.x * 128;
    const int m0 = blockIdx.y * BM;
    const int b  = blockIdx.z;
    const int t = threadIdx.x, w = t >> 5, lane = t & 31;
    const int g = lane >> 2, tig = lane & 3;
    const int wm = w >> 2, wn = w & 3;
    X += (size_t)b * SEQ * CCH;

    __shared__ __align__(16) h16 Wsh[2][BM][40];
    __shared__ __align__(16) h16 Xsh[2][128][40];

    const int wr = t >> 2, wc8 = (t & 3) * 8;
    const h16* wgp = W + (size_t)(m0 + wr) * CCH + wc8;
    const h16* xgp = X + (size_t)(n0 + wr) * CCH + wc8;

    #pragma unroll
    for (int i = 0; i < MF / 2; i++)
        *reinterpret_cast<uint4*>(&Wsh[0][wr + i * 64][wc8]) =
            *reinterpret_cast<const uint4*>(wgp + i * 64 * CCH);
    #pragma unroll
    for (int i = 0; i < 2; i++)
        *reinterpret_cast<uint4*>(&Xsh[0][wr + i * 64][wc8]) =
            *reinterpret_cast<const uint4*>(xgp + i * 64 * CCH);
    __syncthreads();

    float acc[MF][4][4] = {};
    int cur = 0;

    for (int k0 = 0; k0 < CCH; k0 += 32) {
        uint4 pw[MF / 2], px[2];
        const bool nxt = (k0 + 32) < CCH;
        if (nxt) {
            #pragma unroll
            for (int i = 0; i < MF / 2; i++)
                pw[i] = *reinterpret_cast<const uint4*>(wgp + i * 64 * CCH + k0 + 32);
            #pragma unroll
            for (int i = 0; i < 2; i++)
                px[i] = *reinterpret_cast<const uint4*>(xgp + i * 64 * CCH + k0 + 32);
        }

        #pragma unroll
        for (int kc = 0; kc < 2; kc++) {
            unsigned a[MF][4], bb[4][2];
            #pragma unroll
            for (int mf = 0; mf < MF; mf++) {
                int row = wm * (MF * 16) + mf * 16;
                a[mf][0] = *reinterpret_cast<unsigned*>(&Wsh[cur][row + g    ][kc * 16 + 2 * tig    ]);
                a[mf][1] = *reinterpret_cast<unsigned*>(&Wsh[cur][row + g + 8][kc * 16 + 2 * tig    ]);
                a[mf][2] = *reinterpret_cast<unsigned*>(&Wsh[cur][row + g    ][kc * 16 + 2 * tig + 8]);
                a[mf][3] = *reinterpret_cast<unsigned*>(&Wsh[cur][row + g + 8][kc * 16 + 2 * tig + 8]);
            }
            #pragma unroll
            for (int nf = 0; nf < 4; nf++) {
                int row = wn * 32 + nf * 8 + g;
                bb[nf][0] = *reinterpret_cast<unsigned*>(&Xsh[cur][row][kc * 16 + 2 * tig    ]);
                bb[nf][1] = *reinterpret_cast<unsigned*>(&Xsh[cur][row][kc * 16 + 2 * tig + 8]);
            }
            #pragma unroll
            for (int mf = 0; mf < MF; mf++)
                #pragma unroll
                for (int nf = 0; nf < 4; nf++)
                    mmaf16(acc[mf][nf][0], acc[mf][nf][1], acc[mf][nf][2], acc[mf][nf][3],
                           a[mf][0], a[mf][1], a[mf][2], a[mf][3],
                           bb[nf][0], bb[nf][1]);
        }

        if (nxt) {
            #pragma unroll
            for (int i = 0; i < MF / 2; i++)
                *reinterpret_cast<uint4*>(&Wsh[cur ^ 1][wr + i * 64][wc8]) = pw[i];
            #pragma unroll
            for (int i = 0; i < 2; i++)
                *reinterpret_cast<uint4*>(&Xsh[cur ^ 1][wr + i * 64][wc8]) = px[i];
            __syncthreads();
            cur ^= 1;
        }
    }

    // ---- Epilogue (all coalesced packed stores) ----
    const float qscale = 0.17677669529663687f * 1.4426950408889634f;
    #pragma unroll
    for (int mf = 0; mf < MF; mf++) {
        #pragma unroll
        for (int rr = 0; rr < 2; rr++) {
            int m = m0 + wm * (MF * 16) + mf * 16 + g + rr * 8;
            float bz = bias[m];
            #pragma unroll
            for (int nf = 0; nf < 4; nf++) {
                int n = n0 + wn * 32 + nf * 8 + 2 * tig;
                float v0 = acc[mf][nf][rr * 2    ] + bz;
                float v1 = acc[mf][nf][rr * 2 + 1] + bz;
                if (MODE == 1) {
                    size_t off = ((size_t)b * CCH + m) * SEQ + n;
                    float2 rv = *reinterpret_cast<const float2*>(resid + off);
                    float2 o = make_float2(v0 + rv.x, v1 + rv.y);
                    *reinterpret_cast<float2*>(out_f + off) = o;
                } else {
                    if (m < CCH) { v0 *= qscale; v1 *= qscale; }
                    size_t off = ((size_t)b * 3 * CCH + m) * SEQ + n;
                    *reinterpret_cast<unsigned*>(out_h + off) = packh2(v0, v1);
                }
            }
        }
    }
}

// ---------------------------------------------------------------------------
// fp16 flash attention, within-block split-K + software-pipelined chunks.
// Block = 8 warps, 64 queries. Warp (qw, ks): 16 queries, key half ks.
// Steady state per chunk i: ex2(i) -> [ldsmK/V(i+1), QK(i+1)] -> PV(i),
// so every consumer is >= one chunk behind its producer.
// ---------------------------------------------------------------------------
__global__ __launch_bounds__(256) void attn_mma(
    const h16* __restrict__ qkv, h16* __restrict__ aot)
{
    const int t = threadIdx.x, w = t >> 5, lane = t & 31;
    const int g = lane >> 2;
    const int qw = w & 3, ks = w >> 2;
    const int q0 = blockIdx.x * 64;
    const int h  = blockIdx.y;
    const int b  = blockIdx.z;

    const h16* Qb = qkv + ((size_t)b * 3 * CCH + h * HDIM) * SEQ;
    const h16* Kb = Qb + (size_t)CCH * SEQ;
    const h16* Vb = Qb + 2 * (size_t)CCH * SEQ;

    __shared__ __align__(16) h16 Qsh[32][72];
    __shared__ __align__(16) h16 Ksh[2][2][32][72];   // [buf][half][d][key]
    __shared__ __align__(16) h16 Vsh[2][2][32][72];

    // Stage Q tile [d 32][q 64]
    const int kr = t >> 3, kc8 = (t & 7) * 8;
    *reinterpret_cast<uint4*>(&Qsh[kr][kc8]) =
        *reinterpret_cast<const uint4*>(Qb + (size_t)kr * SEQ + q0 + kc8);

    // cp.async first K/V tiles for both halves into buf 0
    const h16* kbase = Kb + (size_t)kr * SEQ + kc8;
    const h16* vbase = Vb + (size_t)kr * SEQ + kc8;
    #pragma unroll
    for (int hs = 0; hs < 2; hs++) {
        cpasync16(su32(&Ksh[0][hs][kr][kc8]), kbase + hs * 2048);
        cpasync16(su32(&Vsh[0][hs][kr][kc8]), vbase + hs * 2048);
    }
    CP_COMMIT();
    __syncthreads();

    // Q fragments via ldmatrix.trans (Qsh is [k][q])
    unsigned aq[2][4];
    #pragma unroll
    for (int kc = 0; kc < 2; kc++) {
        unsigned addr = su32(&Qsh[kc * 16 + ((lane >> 4) & 1) * 8 + (lane & 7)]
                                 [qw * 16 + ((lane >> 3) & 1) * 8]);
        ldsm4t(aq[kc][0], aq[kc][1], aq[kc][2], aq[kc][3], addr);
    }

    unsigned kaddr[2], vaddr[2];
    #pragma unroll
    for (int bu = 0; bu < 2; bu++) {
        kaddr[bu] = su32(&Ksh[bu][ks][lane][0]);
        vaddr[bu] = su32(&Vsh[bu][ks][((lane >> 4) & 1) * 8 + (lane & 7)]
                                    [((lane >> 3) & 1) * 8]);
    }

    float o_acc[4][4] = {};
    float l0 = 0.f, l1 = 0.f;
    int cur = 0;

    for (int k0 = 0; k0 < 2048; k0 += 64) {
        CP_WAIT0();
        __syncthreads();                  // buf cur ready; all warps done with cur^1
        if (k0 + 64 < 2048) {
            #pragma unroll
            for (int hs = 0; hs < 2; hs++) {
                cpasync16(su32(&Ksh[cur ^ 1][hs][kr][kc8]), kbase + hs * 2048 + k0 + 64);
                cpasync16(su32(&Vsh[cur ^ 1][hs][kr][kc8]), vbase + hs * 2048 + k0 + 64);
            }
            CP_COMMIT();
        }

        // ---- Pipelined chunk loop: prologue chunk 0 ----
        float sa[4], sb[4];
        unsigned kv[8];
        {
            unsigned ka0, ka1, ka2, ka3, kb0, kb1, kb2, kb3;
            ldsm4t(ka0, ka1, ka2, ka3, kaddr[cur]);
            ldsm4t(kb0, kb1, kb2, kb3, kaddr[cur] + 16);
            ldsm4(kv[0], kv[1], kv[2], kv[3], vaddr[cur]);
            ldsm4(kv[4], kv[5], kv[6], kv[7], vaddr[cur] + 16 * 144);
            sa[0] = sa[1] = sa[2] = sa[3] = 0.f;
            sb[0] = sb[1] = sb[2] = sb[3] = 0.f;
            mmaf16(sa[0], sa[1], sa[2], sa[3],
                   aq[0][0], aq[0][1], aq[0][2], aq[0][3], ka0, ka1);
            mmaf16(sa[0], sa[1], sa[2], sa[3],
                   aq[1][0], aq[1][1], aq[1][2], aq[1][3], ka2, ka3);
            mmaf16(sb[0], sb[1], sb[2], sb[3],
                   aq[0][0], aq[0][1], aq[0][2], aq[0][3], kb0, kb1);
            mmaf16(sb[0], sb[1], sb[2], sb[3],
                   aq[1][0], aq[1][1], aq[1][2], aq[1][3], kb2, kb3);
        }

        #pragma unroll
        for (int kc2 = 0; kc2 < 4; kc2++) {
            // P = 2^S for chunk kc2 (scores were produced last iteration)
            unsigned pa0 = ex2pair(sa[0], sa[1]);
            unsigned pa1 = ex2pair(sa[2], sa[3]);
            unsigned pa2 = ex2pair(sb[0], sb[1]);
            unsigned pa3 = ex2pair(sb[2], sb[3]);

            // l partials on FMA pipe
            {
                __half2 s01 = __hadd2(*reinterpret_cast<__half2*>(&pa0),
                                      *reinterpret_cast<__half2*>(&pa2));
                __half2 s23 = __hadd2(*reinterpret_cast<__half2*>(&pa1),
                                      *reinterpret_cast<__half2*>(&pa3));
                float2 f01 = __half22float2(s01);
                float2 f23 = __half22float2(s23);
                l0 += f01.x + f01.y;
                l1 += f23.x + f23.y;
            }

            // Prefetch chunk kc2+1: K/V frags + QK scores (independent tensor work
            // that hides the ex2 latency before PV below)
            unsigned cv0 = kv[0], cv1 = kv[1], cv2 = kv[2], cv3 = kv[3];
            unsigned cu0 = kv[4], cu1 = kv[5], cu2 = kv[6], cu3 = kv[7];
            if (kc2 < 3) {
                unsigned ka0, ka1, ka2, ka3, kb0, kb1, kb2, kb3;
                ldsm4t(ka0, ka1, ka2, ka3, kaddr[cur] + (2 * kc2 + 2) * 16);
                ldsm4t(kb0, kb1, kb2, kb3, kaddr[cur] + (2 * kc2 + 3) * 16);
                ldsm4(kv[0], kv[1], kv[2], kv[3], vaddr[cur] + (kc2 + 1) * 32);
                ldsm4(kv[4], kv[5], kv[6], kv[7], vaddr[cur] + (kc2 + 1) * 32 + 16 * 144);
                sa[0] = sa[1] = sa[2] = sa[3] = 0.f;
                sb[0] = sb[1] = sb[2] = sb[3] = 0.f;
                mmaf16(sa[0], sa[1], sa[2], sa[3],
                       aq[0][0], aq[0][1], aq[0][2], aq[0][3], ka0, ka1);
                mmaf16(sa[0], sa[1], sa[2], sa[3],
                       aq[1][0], aq[1][1], aq[1][2], aq[1][3], ka2, ka3);
                mmaf16(sb[0], sb[1], sb[2], sb[3],
                       aq[0][0], aq[0][1], aq[0][2], aq[0][3], kb0, kb1);
                mmaf16(sb[0], sb[1], sb[2], sb[3],
                       aq[1][0], aq[1][1], aq[1][2], aq[1][3], kb2, kb3);
            }

            // O += P V for chunk kc2
            mmaf16(o_acc[0][0], o_acc[0][1], o_acc[0][2], o_acc[0][3],
                   pa0, pa1, pa2, pa3, cv0, cv1);
            mmaf16(o_acc[1][0], o_acc[1][1], o_acc[1][2], o_acc[1][3],
                   pa0, pa1, pa2, pa3, cv2, cv3);
            mmaf16(o_acc[2][0], o_acc[2][1], o_acc[2][2], o_acc[2][3],
                   pa0, pa1, pa2, pa3, cu0, cu1);
            mmaf16(o_acc[3][0], o_acc[3][1], o_acc[3][2], o_acc[3][3],
                   pa0, pa1, pa2, pa3, cu2, cu3);
        }
        cur ^= 1;
    }

    // Quad-reduce l
    l0 += __shfl_xor_sync(0xFFFFFFFFu, l0, 1);
    l0 += __shfl_xor_sync(0xFFFFFFFFu, l0, 2);
    l1 += __shfl_xor_sync(0xFFFFFFFFu, l1, 1);
    l1 += __shfl_xor_sync(0xFFFFFFFFu, l1, 2);

    // Combine key-split halves via fp32 smem (reuse Ksh storage)
    __syncthreads();
    float* ex = reinterpret_cast<float*>(&Ksh[0][0][0][0]);
    const int base = (qw * 32 + lane) * 18;
    if (ks == 1) {
        #pragma unroll
        for (int dc = 0; dc < 4; dc++)
            #pragma unroll
            for (int r = 0; r < 4; r++)
                ex[base + dc * 4 + r] = o_acc[dc][r];
        ex[base + 16] = l0;
        ex[base + 17] = l1;
    }
    __syncthreads();
    if (ks == 0) {
        #pragma unroll
        for (int dc = 0; dc < 4; dc++)
            #pragma unroll
            for (int r = 0; r < 4; r++)
                o_acc[dc][r] += ex[base + dc * 4 + r];
        l0 += ex[base + 16];
        l1 += ex[base + 17];
        float inv0 = 1.f / l0, inv1 = 1.f / l1;

        const int tig = lane & 3;
        const int qa = q0 + qw * 16 + g;
        #pragma unroll
        for (int dc = 0; dc < 4; dc++) {
            int cpos = h * HDIM + dc * 8 + 2 * tig;
            *reinterpret_cast<unsigned*>(aot + ((size_t)b * SEQ + qa    ) * CCH + cpos) =
                packh2(o_acc[dc][0] * inv0, o_acc[dc][1] * inv0);
            *reinterpret_cast<unsigned*>(aot + ((size_t)b * SEQ + qa + 8) * CCH + cpos) =
                packh2(o_acc[dc][2] * inv1, o_acc[dc][3] * inv1);
        }
    }
}

// ---------------------------------------------------------------------------
extern "C" void kernel_launch(void* const* d_in, const int* in_sizes, int n_in,
                              void* d_out, int out_size)
{
    const float* x      = (const float*)d_in[0];
    const float* gamma  = (const float*)d_in[1];
    const float* beta   = (const float*)d_in[2];
    const float* qkv_w  = (const float*)d_in[3];
    const float* qkv_b  = (const float*)d_in[4];
    const float* proj_w = (const float*)d_in[5];
    const float* proj_b = (const float*)d_in[6];
    float* out = (float*)d_out;

    float *st_ptr;
    h16 *ht_ptr, *qkv_ptr, *aot_ptr, *wq_ptr, *wp_ptr;
    cudaGetSymbolAddress((void**)&st_ptr,  g_stats);
    cudaGetSymbolAddress((void**)&ht_ptr,  g_ht);
    cudaGetSymbolAddress((void**)&qkv_ptr, g_qkv);
    cudaGetSymbolAddress((void**)&aot_ptr, g_aot);
    cudaGetSymbolAddress((void**)&wq_ptr,  g_wq);
    cudaGetSymbolAddress((void**)&wp_ptr,  g_wp);

    // 1. GN stats + weight conversion
    prep_kernel<<<64 + (3 * CCH * CCH) / 512, 512>>>(
        x, st_ptr, qkv_w, proj_w, wq_ptr, wp_ptr);

    // 2. Fused normalize+transpose -> ht fp16 [b][s][c]
    normt_kernel<<<dim3(SEQ / 32, CCH / 32, BATCH), 256>>>(x, gamma, beta, st_ptr, ht_ptr);

    // 3. QKV GEMM -> fp16 [b][3C][s] (Q pre-scaled, coalesced packed stores)
    gemm_mma<0, 4><<<dim3(SEQ / 128, (3 * CCH) / 128, BATCH), 256>>>(
        wq_ptr, ht_ptr, qkv_b, nullptr, nullptr, qkv_ptr);

    // 4. Attention (8 warps, 64 q/block, 2-way key split, pipelined chunks)
    attn_mma<<<dim3(SEQ / 64, NHEAD, BATCH), 256>>>(qkv_ptr, aot_ptr);

    // 5. Proj GEMM + bias + residual -> d_out fp32
    gemm_mma<1, 2><<<dim3(SEQ / 128, CCH / 64, BATCH), 256>>>(
        wp_ptr, aot_ptr, proj_b, x, out, nullptr);
}

// round 13
// speedup vs baseline: 1.0162x; 1.0162x over previous
#include <cuda_runtime.h>
#include <cuda_fp16.h>

#define BATCH 2
#define CCH   256
#define NHEAD 8
#define HDIM  32
#define NGRP  32
#define SEQ   4096

typedef __half h16;

// Scratch (allocation-free: __device__ globals)
__device__ float g_stats[BATCH * NGRP * 2];         // mean, rstd per (b,g)
__device__ h16   g_ht[BATCH * SEQ * CCH];           // h transposed [b][s][c]
__device__ h16   g_qkv[BATCH * 3 * CCH * SEQ];      // Q(pre-scaled),K,V [b][3C][s]
__device__ h16   g_aot[BATCH * SEQ * CCH];          // attn out [b][s][c]
__device__ h16   g_wq[3 * CCH * CCH];               // qkv_w fp16
__device__ h16   g_wp[CCH * CCH];                   // proj_w fp16

__device__ __forceinline__ void mmaf16(
    float& d0, float& d1, float& d2, float& d3,
    unsigned a0, unsigned a1, unsigned a2, unsigned a3,
    unsigned b0, unsigned b1)
{
    asm volatile(
        "mma.sync.aligned.m16n8k16.row.col.f32.f16.f16.f32 "
        "{%0,%1,%2,%3}, {%4,%5,%6,%7}, {%8,%9}, {%0,%1,%2,%3};"
        : "+f"(d0), "+f"(d1), "+f"(d2), "+f"(d3)
        : "r"(a0), "r"(a1), "r"(a2), "r"(a3), "r"(b0), "r"(b1));
}

__device__ __forceinline__ unsigned packh2(float lo, float hi) {
    __half2 p = __floats2half2_rn(lo, hi);
    return *reinterpret_cast<unsigned*>(&p);
}

// pack two f32 scores to f16x2, then 2^x on both halves with ONE MUFU op
__device__ __forceinline__ unsigned ex2pair(float lo, float hi) {
    unsigned c, y;
    asm("cvt.rn.f16x2.f32 %0, %1, %2;" : "=r"(c) : "f"(hi), "f"(lo));
    asm("ex2.approx.f16x2 %0, %1;" : "=r"(y) : "r"(c));
    return y;
}

__device__ __forceinline__ unsigned su32(const void* p) {
    return (unsigned)__cvta_generic_to_shared(p);
}
__device__ __forceinline__ void ldsm4(unsigned& r0, unsigned& r1, unsigned& r2,
                                      unsigned& r3, unsigned a) {
    asm volatile("ldmatrix.sync.aligned.m8n8.x4.shared.b16 {%0,%1,%2,%3},[%4];"
                 : "=r"(r0), "=r"(r1), "=r"(r2), "=r"(r3) : "r"(a));
}
__device__ __forceinline__ void ldsm4t(unsigned& r0, unsigned& r1, unsigned& r2,
                                       unsigned& r3, unsigned a) {
    asm volatile("ldmatrix.sync.aligned.m8n8.x4.trans.shared.b16 {%0,%1,%2,%3},[%4];"
                 : "=r"(r0), "=r"(r1), "=r"(r2), "=r"(r3) : "r"(a));
}
__device__ __forceinline__ void cpasync16(unsigned dst, const void* src) {
    asm volatile("cp.async.cg.shared.global [%0], [%1], 16;" :: "r"(dst), "l"(src));
}
#define CP_COMMIT() asm volatile("cp.async.commit_group;" ::: "memory")
#define CP_WAIT0()  asm volatile("cp.async.wait_group 0;" ::: "memory")

// ---------------------------------------------------------------------------
// Prep: blocks [0,64) -> GN stats; blocks [64,448) -> weights fp16
// ---------------------------------------------------------------------------
__global__ __launch_bounds__(512) void prep_kernel(
    const float* __restrict__ x, float* __restrict__ stats,
    const float* __restrict__ qw, const float* __restrict__ pw,
    h16* __restrict__ oq, h16* __restrict__ op)
{
    const int tid = threadIdx.x;
    if (blockIdx.x >= 64) {
        int i = (blockIdx.x - 64) * 512 + tid;
        oq[i] = __float2half(qw[i]);
        if (i < CCH * CCH) op[i] = __float2half(pw[i]);
        return;
    }
    const int g = blockIdx.x & 31, b = blockIdx.x >> 5;
    const float4* xp = reinterpret_cast<const float4*>(x + ((size_t)b * CCH + g * 8) * SEQ);

    float s = 0.f, s2 = 0.f;
    #pragma unroll 4
    for (int i = tid; i < 8192; i += 512) {
        float4 v = xp[i];
        s  += v.x + v.y + v.z + v.w;
        s2 += v.x * v.x + v.y * v.y + v.z * v.z + v.w * v.w;
    }
    #pragma unroll
    for (int o = 16; o; o >>= 1) {
        s  += __shfl_xor_sync(0xFFFFFFFFu, s, o);
        s2 += __shfl_xor_sync(0xFFFFFFFFu, s2, o);
    }
    __shared__ float ss[16], ss2[16];
    int w = tid >> 5;
    if ((tid & 31) == 0) { ss[w] = s; ss2[w] = s2; }
    __syncthreads();
    if (tid == 0) {
        float a = 0.f, a2 = 0.f;
        #pragma unroll
        for (int j = 0; j < 16; j++) { a += ss[j]; a2 += ss2[j]; }
        const float invN = 1.f / 32768.f;
        float mean = a * invN;
        float var  = a2 * invN - mean * mean;
        stats[(b * NGRP + g) * 2]     = mean;
        stats[(b * NGRP + g) * 2 + 1] = rsqrtf(var + 1e-6f);
    }
}

// ---------------------------------------------------------------------------
// Fused normalize + transpose: x fp32 [b][c][s] -> ht fp16 [b][s][c]
// ---------------------------------------------------------------------------
__global__ __launch_bounds__(256) void normt_kernel(
    const float* __restrict__ x, const float* __restrict__ gamma,
    const float* __restrict__ beta, const float* __restrict__ stats,
    h16* __restrict__ out)
{
    const int s0 = blockIdx.x * 32, c0 = blockIdx.y * 32, b = blockIdx.z;
    __shared__ float T[32][33];
    const int t = threadIdx.x;
    {
        int r = t >> 3, cc = (t & 7) * 4;
        int c = c0 + r;
        int grp = c >> 3;
        float mean = stats[(b * NGRP + grp) * 2];
        float rstd = stats[(b * NGRP + grp) * 2 + 1];
        float ga = gamma[c] * rstd;
        float be = beta[c] - mean * ga;
        float4 v = *reinterpret_cast<const float4*>(
            x + ((size_t)b * CCH + c) * SEQ + s0 + cc);
        T[r][cc]     = v.x * ga + be;
        T[r][cc + 1] = v.y * ga + be;
        T[r][cc + 2] = v.z * ga + be;
        T[r][cc + 3] = v.w * ga + be;
    }
    __syncthreads();
    {
        int sr = t >> 3, c4 = (t & 7) * 4;
        uint2 u;
        u.x = packh2(T[c4][sr], T[c4 + 1][sr]);
        u.y = packh2(T[c4 + 2][sr], T[c4 + 3][sr]);
        *reinterpret_cast<uint2*>(out + ((size_t)b * SEQ + s0 + sr) * CCH + c0 + c4) = u;
    }
}

// ---------------------------------------------------------------------------
// fp16 tensor-core GEMM, double-buffered. Block tile (MF*32) x 128, 8 warps.
// MODE 0 (MF=4): qkv -> fp16 [b][3C][s], Q rows pre-scaled by log2(e)/sqrt(d)
// MODE 1 (MF=2): proj -> fp32 out = acc + bias + residual
// ---------------------------------------------------------------------------
template<int MODE, int MF>
__global__ __launch_bounds__(256, 2) void gemm_mma(
    const h16* __restrict__ W, const h16* __restrict__ X,
    const float* __restrict__ bias, const float* __restrict__ resid,
    float* __restrict__ out_f, h16* __restrict__ out_h)
{
    const int BM = MF * 32;
    const int n0 = blockIdx.x * 128;
    const int m0 = blockIdx.y * BM;
    const int b  = blockIdx.z;
    const int t = threadIdx.x, w = t >> 5, lane = t & 31;
    const int g = lane >> 2, tig = lane & 3;
    const int wm = w >> 2, wn = w & 3;
    X += (size_t)b * SEQ * CCH;

    __shared__ __align__(16) h16 Wsh[2][BM][40];
    __shared__ __align__(16) h16 Xsh[2][128][40];

    const int wr = t >> 2, wc8 = (t & 3) * 8;
    const h16* wgp = W + (size_t)(m0 + wr) * CCH + wc8;
    const h16* xgp = X + (size_t)(n0 + wr) * CCH + wc8;

    #pragma unroll
    for (int i = 0; i < MF / 2; i++)
        *reinterpret_cast<uint4*>(&Wsh[0][wr + i * 64][wc8]) =
            *reinterpret_cast<const uint4*>(wgp + i * 64 * CCH);
    #pragma unroll
    for (int i = 0; i < 2; i++)
        *reinterpret_cast<uint4*>(&Xsh[0][wr + i * 64][wc8]) =
            *reinterpret_cast<const uint4*>(xgp + i * 64 * CCH);
    __syncthreads();

    float acc[MF][4][4] = {};
    int cur = 0;

    for (int k0 = 0; k0 < CCH; k0 += 32) {
        uint4 pw[MF / 2], px[2];
        const bool nxt = (k0 + 32) < CCH;
        if (nxt) {
            #pragma unroll
            for (int i = 0; i < MF / 2; i++)
                pw[i] = *reinterpret_cast<const uint4*>(wgp + i * 64 * CCH + k0 + 32);
            #pragma unroll
            for (int i = 0; i < 2; i++)
                px[i] = *reinterpret_cast<const uint4*>(xgp + i * 64 * CCH + k0 + 32);
        }

        #pragma unroll
        for (int kc = 0; kc < 2; kc++) {
            unsigned a[MF][4], bb[4][2];
            #pragma unroll
            for (int mf = 0; mf < MF; mf++) {
                int row = wm * (MF * 16) + mf * 16;
                a[mf][0] = *reinterpret_cast<unsigned*>(&Wsh[cur][row + g    ][kc * 16 + 2 * tig    ]);
                a[mf][1] = *reinterpret_cast<unsigned*>(&Wsh[cur][row + g + 8][kc * 16 + 2 * tig    ]);
                a[mf][2] = *reinterpret_cast<unsigned*>(&Wsh[cur][row + g    ][kc * 16 + 2 * tig + 8]);
                a[mf][3] = *reinterpret_cast<unsigned*>(&Wsh[cur][row + g + 8][kc * 16 + 2 * tig + 8]);
            }
            #pragma unroll
            for (int nf = 0; nf < 4; nf++) {
                int row = wn * 32 + nf * 8 + g;
                bb[nf][0] = *reinterpret_cast<unsigned*>(&Xsh[cur][row][kc * 16 + 2 * tig    ]);
                bb[nf][1] = *reinterpret_cast<unsigned*>(&Xsh[cur][row][kc * 16 + 2 * tig + 8]);
            }
            #pragma unroll
            for (int mf = 0; mf < MF; mf++)
                #pragma unroll
                for (int nf = 0; nf < 4; nf++)
                    mmaf16(acc[mf][nf][0], acc[mf][nf][1], acc[mf][nf][2], acc[mf][nf][3],
                           a[mf][0], a[mf][1], a[mf][2], a[mf][3],
                           bb[nf][0], bb[nf][1]);
        }

        if (nxt) {
            #pragma unroll
            for (int i = 0; i < MF / 2; i++)
                *reinterpret_cast<uint4*>(&Wsh[cur ^ 1][wr + i * 64][wc8]) = pw[i];
            #pragma unroll
            for (int i = 0; i < 2; i++)
                *reinterpret_cast<uint4*>(&Xsh[cur ^ 1][wr + i * 64][wc8]) = px[i];
            __syncthreads();
            cur ^= 1;
        }
    }

    // ---- Epilogue (all coalesced packed stores) ----
    const float qscale = 0.17677669529663687f * 1.4426950408889634f;
    #pragma unroll
    for (int mf = 0; mf < MF; mf++) {
        #pragma unroll
        for (int rr = 0; rr < 2; rr++) {
            int m = m0 + wm * (MF * 16) + mf * 16 + g + rr * 8;
            float bz = bias[m];
            #pragma unroll
            for (int nf = 0; nf < 4; nf++) {
                int n = n0 + wn * 32 + nf * 8 + 2 * tig;
                float v0 = acc[mf][nf][rr * 2    ] + bz;
                float v1 = acc[mf][nf][rr * 2 + 1] + bz;
                if (MODE == 1) {
                    size_t off = ((size_t)b * CCH + m) * SEQ + n;
                    float2 rv = *reinterpret_cast<const float2*>(resid + off);
                    float2 o = make_float2(v0 + rv.x, v1 + rv.y);
                    *reinterpret_cast<float2*>(out_f + off) = o;
                } else {
                    if (m < CCH) { v0 *= qscale; v1 *= qscale; }
                    size_t off = ((size_t)b * 3 * CCH + m) * SEQ + n;
                    *reinterpret_cast<unsigned*>(out_h + off) = packh2(v0, v1);
                }
            }
        }
    }
}

// ---------------------------------------------------------------------------
// fp16 flash attention, within-block split-K. Block = 8 warps, 64 queries.
// Warp (qw, ks): 16 queries, key half ks*[0,2048). __launch_bounds__(256,4)
// forces regs<=64 so 4 blocks/SM co-reside (supply-limited HMMA pipe).
// ---------------------------------------------------------------------------
__global__ __launch_bounds__(256, 4) void attn_mma(
    const h16* __restrict__ qkv, h16* __restrict__ aot)
{
    const int t = threadIdx.x, w = t >> 5, lane = t & 31;
    const int g = lane >> 2;
    const int qw = w & 3, ks = w >> 2;
    const int q0 = blockIdx.x * 64;
    const int h  = blockIdx.y;
    const int b  = blockIdx.z;

    const h16* Qb = qkv + ((size_t)b * 3 * CCH + h * HDIM) * SEQ;
    const h16* Kb = Qb + (size_t)CCH * SEQ;
    const h16* Vb = Qb + 2 * (size_t)CCH * SEQ;

    __shared__ __align__(16) h16 Qsh[32][72];
    __shared__ __align__(16) h16 Ksh[2][2][32][72];   // [buf][half][d][key]
    __shared__ __align__(16) h16 Vsh[2][2][32][72];
    const int BUFSTR = 2 * 32 * 72 * 2;               // 9216 B per buffer

    // Stage Q tile [d 32][q 64]
    const int kr = t >> 3, kc8 = (t & 7) * 8;
    *reinterpret_cast<uint4*>(&Qsh[kr][kc8]) =
        *reinterpret_cast<const uint4*>(Qb + (size_t)kr * SEQ + q0 + kc8);

    // cp.async first K/V tiles for both halves into buf 0
    const h16* kbase = Kb + (size_t)kr * SEQ + kc8;
    const h16* vbase = Vb + (size_t)kr * SEQ + kc8;
    #pragma unroll
    for (int hs = 0; hs < 2; hs++) {
        cpasync16(su32(&Ksh[0][hs][kr][kc8]), kbase + hs * 2048);
        cpasync16(su32(&Vsh[0][hs][kr][kc8]), vbase + hs * 2048);
    }
    CP_COMMIT();
    __syncthreads();

    // Q fragments via ldmatrix.trans (Qsh is [k][q])
    unsigned aq[2][4];
    #pragma unroll
    for (int kc = 0; kc < 2; kc++) {
        unsigned addr = su32(&Qsh[kc * 16 + ((lane >> 4) & 1) * 8 + (lane & 7)]
                                 [qw * 16 + ((lane >> 3) & 1) * 8]);
        ldsm4t(aq[kc][0], aq[kc][1], aq[kc][2], aq[kc][3], addr);
    }

    const unsigned kaddr0 = su32(&Ksh[0][ks][lane][0]);
    const unsigned vaddr0 = su32(&Vsh[0][ks][((lane >> 4) & 1) * 8 + (lane & 7)]
                                           [((lane >> 3) & 1) * 8]);

    float o_acc[4][4] = {};
    float l0 = 0.f, l1 = 0.f;
    int cur = 0;

    for (int k0 = 0; k0 < 2048; k0 += 64) {
        CP_WAIT0();
        __syncthreads();                  // buf cur ready; all warps done with cur^1
        if (k0 + 64 < 2048) {
            #pragma unroll
            for (int hs = 0; hs < 2; hs++) {
                cpasync16(su32(&Ksh[cur ^ 1][hs][kr][kc8]), kbase + hs * 2048 + k0 + 64);
                cpasync16(su32(&Vsh[cur ^ 1][hs][kr][kc8]), vbase + hs * 2048 + k0 + 64);
            }
            CP_COMMIT();
        }
        const unsigned kaddr = kaddr0 + cur * BUFSTR;
        const unsigned vaddr = vaddr0 + cur * BUFSTR;

        #pragma unroll
        for (int kc2 = 0; kc2 < 4; kc2++) {
            // K fragments for keys [kc2*16, kc2*16+16) of this warp's half
            unsigned ka0, ka1, ka2, ka3, kb0, kb1, kb2, kb3;
            ldsm4t(ka0, ka1, ka2, ka3, kaddr + (2 * kc2    ) * 16);
            ldsm4t(kb0, kb1, kb2, kb3, kaddr + (2 * kc2 + 1) * 16);

            // S = Q K^T (log2 domain)
            float sa[4] = {}, sb[4] = {};
            mmaf16(sa[0], sa[1], sa[2], sa[3],
                   aq[0][0], aq[0][1], aq[0][2], aq[0][3], ka0, ka1);
            mmaf16(sa[0], sa[1], sa[2], sa[3],
                   aq[1][0], aq[1][1], aq[1][2], aq[1][3], ka2, ka3);
            mmaf16(sb[0], sb[1], sb[2], sb[3],
                   aq[0][0], aq[0][1], aq[0][2], aq[0][3], kb0, kb1);
            mmaf16(sb[0], sb[1], sb[2], sb[3],
                   aq[1][0], aq[1][1], aq[1][2], aq[1][3], kb2, kb3);

            // P = 2^S packed into PV A-fragments
            unsigned pa0 = ex2pair(sa[0], sa[1]);
            unsigned pa1 = ex2pair(sa[2], sa[3]);
            unsigned pa2 = ex2pair(sb[0], sb[1]);
            unsigned pa3 = ex2pair(sb[2], sb[3]);

            // l partials on FMA pipe
            {
                __half2 s01 = __hadd2(*reinterpret_cast<__half2*>(&pa0),
                                      *reinterpret_cast<__half2*>(&pa2));
                __half2 s23 = __hadd2(*reinterpret_cast<__half2*>(&pa1),
                                      *reinterpret_cast<__half2*>(&pa3));
                float2 f01 = __half22float2(s01);
                float2 f23 = __half22float2(s23);
                l0 += f01.x + f01.y;
                l1 += f23.x + f23.y;
            }

            // V fragments, O += P V
            unsigned v0, v1, v2, v3, u0, u1, u2, u3;
            ldsm4(v0, v1, v2, v3, vaddr + kc2 * 32);
            ldsm4(u0, u1, u2, u3, vaddr + kc2 * 32 + 16 * 144);
            mmaf16(o_acc[0][0], o_acc[0][1], o_acc[0][2], o_acc[0][3],
                   pa0, pa1, pa2, pa3, v0, v1);
            mmaf16(o_acc[1][0], o_acc[1][1], o_acc[1][2], o_acc[1][3],
                   pa0, pa1, pa2, pa3, v2, v3);
            mmaf16(o_acc[2][0], o_acc[2][1], o_acc[2][2], o_acc[2][3],
                   pa0, pa1, pa2, pa3, u0, u1);
            mmaf16(o_acc[3][0], o_acc[3][1], o_acc[3][2], o_acc[3][3],
                   pa0, pa1, pa2, pa3, u2, u3);
        }
        cur ^= 1;
    }

    // Quad-reduce l
    l0 += __shfl_xor_sync(0xFFFFFFFFu, l0, 1);
    l0 += __shfl_xor_sync(0xFFFFFFFFu, l0, 2);
    l1 += __shfl_xor_sync(0xFFFFFFFFu, l1, 1);
    l1 += __shfl_xor_sync(0xFFFFFFFFu, l1, 2);

    // Combine key-split halves via fp32 smem (reuse Ksh storage)
    __syncthreads();
    float* ex = reinterpret_cast<float*>(&Ksh[0][0][0][0]);
    const int base = (qw * 32 + lane) * 18;
    if (ks == 1) {
        #pragma unroll
        for (int dc = 0; dc < 4; dc++)
            #pragma unroll
            for (int r = 0; r < 4; r++)
                ex[base + dc * 4 + r] = o_acc[dc][r];
        ex[base + 16] = l0;
        ex[base + 17] = l1;
    }
    __syncthreads();
    if (ks == 0) {
        #pragma unroll
        for (int dc = 0; dc < 4; dc++)
            #pragma unroll
            for (int r = 0; r < 4; r++)
                o_acc[dc][r] += ex[base + dc * 4 + r];
        l0 += ex[base + 16];
        l1 += ex[base + 17];
        float inv0 = 1.f / l0, inv1 = 1.f / l1;

        const int tig = lane & 3;
        const int qa = q0 + qw * 16 + g;
        #pragma unroll
        for (int dc = 0; dc < 4; dc++) {
            int cpos = h * HDIM + dc * 8 + 2 * tig;
            *reinterpret_cast<unsigned*>(aot + ((size_t)b * SEQ + qa    ) * CCH + cpos) =
                packh2(o_acc[dc][0] * inv0, o_acc[dc][1] * inv0);
            *reinterpret_cast<unsigned*>(aot + ((size_t)b * SEQ + qa + 8) * CCH + cpos) =
                packh2(o_acc[dc][2] * inv1, o_acc[dc][3] * inv1);
        }
    }
}

// ---------------------------------------------------------------------------
extern "C" void kernel_launch(void* const* d_in, const int* in_sizes, int n_in,
                              void* d_out, int out_size)
{
    const float* x      = (const float*)d_in[0];
    const float* gamma  = (const float*)d_in[1];
    const float* beta   = (const float*)d_in[2];
    const float* qkv_w  = (const float*)d_in[3];
    const float* qkv_b  = (const float*)d_in[4];
    const float* proj_w = (const float*)d_in[5];
    const float* proj_b = (const float*)d_in[6];
    float* out = (float*)d_out;

    float *st_ptr;
    h16 *ht_ptr, *qkv_ptr, *aot_ptr, *wq_ptr, *wp_ptr;
    cudaGetSymbolAddress((void**)&st_ptr,  g_stats);
    cudaGetSymbolAddress((void**)&ht_ptr,  g_ht);
    cudaGetSymbolAddress((void**)&qkv_ptr, g_qkv);
    cudaGetSymbolAddress((void**)&aot_ptr, g_aot);
    cudaGetSymbolAddress((void**)&wq_ptr,  g_wq);
    cudaGetSymbolAddress((void**)&wp_ptr,  g_wp);

    // 1. GN stats + weight conversion
    prep_kernel<<<64 + (3 * CCH * CCH) / 512, 512>>>(
        x, st_ptr, qkv_w, proj_w, wq_ptr, wp_ptr);

    // 2. Fused normalize+transpose -> ht fp16 [b][s][c]
    normt_kernel<<<dim3(SEQ / 32, CCH / 32, BATCH), 256>>>(x, gamma, beta, st_ptr, ht_ptr);

    // 3. QKV GEMM -> fp16 [b][3C][s] (Q pre-scaled, coalesced packed stores)
    gemm_mma<0, 4><<<dim3(SEQ / 128, (3 * CCH) / 128, BATCH), 256>>>(
        wq_ptr, ht_ptr, qkv_b, nullptr, nullptr, qkv_ptr);

    // 4. Attention (8 warps, 64 q/block, 2-way key split, 4 blocks/SM)
    attn_mma<<<dim3(SEQ / 64, NHEAD, BATCH), 256>>>(qkv_ptr, aot_ptr);

    // 5. Proj GEMM + bias + residual -> d_out fp32
    gemm_mma<1, 2><<<dim3(SEQ / 128, CCH / 64, BATCH), 256>>>(
        wp_ptr, aot_ptr, proj_b, x, out, nullptr);
}